// round 1
// baseline (speedup 1.0000x reference)
#include <cuda_runtime.h>

#define T_STEPS 32
#define BB      32
#define NIN     512
#define NH      1024
#define NOUT    256
#define NBLK    148
#define NTHR    256
#define KC      64

// ---------------- device scratch (no allocations allowed) ----------------
__device__ float g_hist[T_STEPS][BB][NH];   // pre-norm h history (4 MB)
__device__ float g_h[BB][NH];               // carry (normalized hs)
__device__ float g_sP[2][BB][NH];
__device__ float g_hWP[2][BB][NH];
__device__ float g_zP[4][BB][NH];
__device__ float g_zcP[4][BB][NH];
__device__ float g_zc[BB][NH];
__device__ float g_hsP[4][BB][NH];
__device__ float g_dots[T_STEPS][BB];
__device__ unsigned g_cnt;                  // monotonic barrier counter

// ---------------- f32x2 helpers (Blackwell packed fp32) ----------------
__device__ __forceinline__ unsigned long long pk2(float lo, float hi) {
    unsigned long long r;
    asm("mov.b64 %0, {%1, %2};" : "=l"(r) : "f"(lo), "f"(hi));
    return r;
}
__device__ __forceinline__ void upk2(unsigned long long v, float& lo, float& hi) {
    asm("mov.b64 {%0, %1}, %2;" : "=f"(lo), "=f"(hi) : "l"(v));
}
__device__ __forceinline__ unsigned long long fma2(unsigned long long a,
                                                   unsigned long long b,
                                                   unsigned long long c) {
    unsigned long long d;
    asm("fma.rn.f32x2 %0, %1, %2, %3;" : "=l"(d) : "l"(a), "l"(b), "l"(c));
    return d;
}

// ---------------- grid barrier (monotonic counter, no reset race) --------
__device__ __forceinline__ void gsync() {
    __syncthreads();
    if (threadIdx.x == 0) {
        __threadfence();
        unsigned arrival = atomicAdd(&g_cnt, 1u);
        unsigned target  = (arrival / NBLK + 1u) * NBLK;
        while (*(volatile unsigned*)&g_cnt < target) { }
        __threadfence();
    }
    __syncthreads();
}

// ---------------- 32xK x Kx32-chunk GEMM tile --------------------------
// out[b][j] = sum_{k in [k0,k0+klen)} A[b][k] * W[k][j],  j in chunk*32..+31
// A is combined from up to 4 partial buffers with optional relu at staging.
template<int NSUM, bool RELU>
__device__ __forceinline__ void gemm32(float (*As)[34],
    const float* __restrict__ A0, const float* __restrict__ A1,
    const float* __restrict__ A2, const float* __restrict__ A3,
    int KA, const float* __restrict__ W, int N, int k0, int klen,
    float* __restrict__ outp, int chunk)
{
    const int tid  = threadIdx.x;
    const int lane = tid & 31;
    const int wg   = tid >> 5;          // 8 warps -> 4 rows each
    const int j    = chunk * 32 + lane;
    const int r0   = wg * 4;
    unsigned long long acc01 = 0ULL, acc23 = 0ULL;

    for (int kb = 0; kb < klen; kb += KC) {
        __syncthreads();
        // stage A (transposed, padded): As[k][b]
#pragma unroll
        for (int u = 0; u < (KC * BB) / NTHR; ++u) {
            int idx = u * NTHR + tid;
            int b   = idx >> 6;          // KC = 64
            int kk  = idx & (KC - 1);
            int gk  = k0 + kb + kk;
            float v = A0[b * KA + gk];
            if (NSUM > 1) v += A1[b * KA + gk];
            if (NSUM > 2) v += A2[b * KA + gk];
            if (NSUM > 3) v += A3[b * KA + gk];
            if (RELU) v = fmaxf(v, 0.0f);
            As[kk][b] = v;
        }
        __syncthreads();
        const float* Wp = W + (size_t)(k0 + kb) * N + j;
#pragma unroll 8
        for (int kk = 0; kk < KC; ++kk) {
            float w = Wp[(size_t)kk * N];               // coalesced across lanes
            unsigned long long w2  = pk2(w, w);
            unsigned long long a01 = *(const unsigned long long*)&As[kk][r0];
            unsigned long long a23 = *(const unsigned long long*)&As[kk][r0 + 2];
            acc01 = fma2(a01, w2, acc01);
            acc23 = fma2(a23, w2, acc23);
        }
    }
    float s0, s1, s2, s3;
    upk2(acc01, s0, s1);
    upk2(acc23, s2, s3);
    outp[(r0 + 0) * N + j] = s0;
    outp[(r0 + 1) * N + j] = s1;
    outp[(r0 + 2) * N + j] = s2;
    outp[(r0 + 3) * N + j] = s3;
}

// ---------------- persistent kernel ------------------------------------
__global__ void __launch_bounds__(NTHR, 1) memnet_kernel(
    const float* __restrict__ x_in,  const float* __restrict__ W_i,
    const float* __restrict__ W_z,   const float* __restrict__ W_c,
    const float* __restrict__ W_h,   const float* __restrict__ W_ho,
    const float* __restrict__ W_o,   const float* __restrict__ lam_p,
    const float* __restrict__ eta_p, const float* __restrict__ g_p,
    const float* __restrict__ b_p,   float* __restrict__ y_out)
{
    __shared__ float As[KC][34];
    __shared__ float red_s[8][32];
    __shared__ float red_q[8][32];

    const int tid  = threadIdx.x;
    const int bid  = blockIdx.x;
    const int lane = tid & 31;
    const int wg   = tid >> 5;
    const int gtid = bid * NTHR + tid;
    const int gstr = NBLK * NTHR;

    // phase 0: zero the carry
    for (int i = gtid; i < BB * NH; i += gstr) (&g_h[0][0])[i] = 0.0f;
    gsync();

    const float lamv = lam_p[0];
    const float etav = eta_p[0];

    for (int t = 0; t < T_STEPS; ++t) {
        const float* xt = x_in + (size_t)t * BB * NIN;

        // ---- P1: s partials (relu(x)@W_i) + hW partials (h@W_h) : 128 tasks
        for (int task = bid; task < 128; task += NBLK) {
            if (task < 64) {
                int chunk = task >> 1, kh = task & 1;
                gemm32<1, true >(As, xt, 0, 0, 0, NIN, W_i, NH,
                                 kh * 256, 256, &g_sP[kh][0][0], chunk);
            } else {
                int tt = task - 64;
                int chunk = tt >> 1, kh = tt & 1;
                gemm32<1, false>(As, &g_h[0][0], 0, 0, 0, NH, W_h, NH,
                                 kh * 512, 512, &g_hWP[kh][0][0], chunk);
            }
        }
        gsync();

        // ---- P2: z partials = relu(s) @ W_z   (s combined+relu at staging)
        for (int task = bid; task < 128; task += NBLK) {
            int chunk = task >> 2, ks = task & 3;
            gemm32<2, true>(As, &g_sP[0][0][0], &g_sP[1][0][0], 0, 0, NH,
                            W_z, NH, ks * 256, 256, &g_zP[ks][0][0], chunk);
        }
        gsync();

        // ---- P3: zc partials = relu(z) @ W_c
        for (int task = bid; task < 128; task += NBLK) {
            int chunk = task >> 2, ks = task & 3;
            gemm32<4, true>(As, &g_zP[0][0][0], &g_zP[1][0][0],
                            &g_zP[2][0][0], &g_zP[3][0][0], NH,
                            W_c, NH, ks * 256, 256, &g_zcP[ks][0][0], chunk);
        }
        gsync();

        // ---- P4: elementwise  h_new = relu(zc + hW), keep zc
        {
            const float* zc0 = &g_zcP[0][0][0]; const float* zc1 = &g_zcP[1][0][0];
            const float* zc2 = &g_zcP[2][0][0]; const float* zc3 = &g_zcP[3][0][0];
            const float* hw0 = &g_hWP[0][0][0]; const float* hw1 = &g_hWP[1][0][0];
            float* zcs = &g_zc[0][0];
            float* hn  = &g_hist[t][0][0];
            for (int i = gtid; i < BB * NH; i += gstr) {
                float zc = (zc0[i] + zc1[i]) + (zc2[i] + zc3[i]);
                float hw = hw0[i] + hw1[i];
                zcs[i] = zc;
                hn[i]  = fmaxf(zc + hw, 0.0f);
            }
        }
        gsync();

        // ---- P5: hs partials = h_new @ W_h  (128 tasks) + history dots
        for (int task = bid; task < 128; task += NBLK) {
            int chunk = task >> 2, ks = task & 3;
            gemm32<1, false>(As, &g_hist[t][0][0], 0, 0, 0, NH, W_h, NH,
                             ks * 256, 256, &g_hsP[ks][0][0], chunk);
        }
        if (bid >= 128) {   // 20 blocks x 8 warps compute the (t+1)*32 dots
            int widg = (bid - 128) * 8 + wg;
            int nd = (t + 1) * BB;
            for (int d = widg; d < nd; d += 20 * 8) {
                int s = d >> 5, b = d & 31;
                const float* ha = &g_hist[t][b][0];
                const float* hb = &g_hist[s][b][0];
                float sum = 0.0f;
#pragma unroll
                for (int jj = lane * 4; jj < NH; jj += 128) {
                    float4 a = *(const float4*)(ha + jj);
                    float4 c = *(const float4*)(hb + jj);
                    sum += a.x * c.x + a.y * c.y + a.z * c.z + a.w * c.w;
                }
#pragma unroll
                for (int off = 16; off; off >>= 1)
                    sum += __shfl_xor_sync(0xffffffffu, sum, off);
                if (lane == 0) g_dots[s][b] = sum;
            }
        }
        gsync();

        // ---- P6: hs = hsW + zc + eta*sum_s lam^(t-s)*dot*hist ; batchnorm ; relu
        for (int task = bid; task < 32; task += NBLK) {
            int j = task * 32 + lane;
            float gv = g_p[j], bv = b_p[j];
            float v[4];
#pragma unroll
            for (int r = 0; r < 4; ++r) {
                int b = wg * 4 + r;
                float base = (g_hsP[0][b][j] + g_hsP[1][b][j]) +
                             (g_hsP[2][b][j] + g_hsP[3][b][j]) + g_zc[b][j];
                float accr = 0.0f, p = 1.0f;
                for (int s = t; s >= 0; --s) {
                    accr += p * g_dots[s][b] * g_hist[s][b][j];
                    p *= lamv;
                }
                v[r] = base + etav * accr;
            }
            float ps = 0.0f, pq = 0.0f;
#pragma unroll
            for (int r = 0; r < 4; ++r) { ps += v[r]; pq += v[r] * v[r]; }
            red_s[wg][lane] = ps;
            red_q[wg][lane] = pq;
            __syncthreads();
            float mu = 0.0f, sq = 0.0f;
#pragma unroll
            for (int w = 0; w < 8; ++w) { mu += red_s[w][lane]; sq += red_q[w][lane]; }
            mu *= (1.0f / BB);
            sq *= (1.0f / BB);
            float sig = sqrtf(fmaxf(sq - mu * mu, 0.0f));
#pragma unroll
            for (int r = 0; r < 4; ++r) {
                float hv = fmaxf(gv * (v[r] - mu) / sig + bv, 0.0f);
                g_h[wg * 4 + r][j] = hv;
            }
            __syncthreads();
        }
        gsync();
    }

    // ---- F1: o partials = h @ W_ho   (relu at F2 staging) — reuse g_zP
    for (int task = bid; task < 128; task += NBLK) {
        int chunk = task >> 2, ks = task & 3;
        gemm32<1, false>(As, &g_h[0][0], 0, 0, 0, NH, W_ho, NH,
                         ks * 256, 256, &g_zP[ks][0][0], chunk);
    }
    gsync();

    // ---- F2: y partials = relu(o) @ W_o  (N=256: 8 chunks x 4 ksplit)
    for (int task = bid; task < 32; task += NBLK) {
        int chunk = task >> 2, ks = task & 3;
        gemm32<4, true>(As, &g_zP[0][0][0], &g_zP[1][0][0],
                        &g_zP[2][0][0], &g_zP[3][0][0], NH,
                        W_o, NOUT, ks * 256, 256,
                        (&g_zcP[0][0][0]) + (size_t)ks * BB * NOUT, chunk);
    }
    gsync();

    // ---- F3: y = relu(sum partials)
    {
        const float* yp = &g_zcP[0][0][0];
        for (int i = gtid; i < BB * NOUT; i += gstr) {
            float v = (yp[i] + yp[BB * NOUT + i]) +
                      (yp[2 * BB * NOUT + i] + yp[3 * BB * NOUT + i]);
            y_out[i] = fmaxf(v, 0.0f);
        }
    }
}

// ---------------- launch ----------------
extern "C" void kernel_launch(void* const* d_in, const int* in_sizes, int n_in,
                              void* d_out, int out_size) {
    (void)in_sizes; (void)n_in; (void)out_size;
    memnet_kernel<<<NBLK, NTHR>>>(
        (const float*)d_in[0],  (const float*)d_in[1], (const float*)d_in[2],
        (const float*)d_in[3],  (const float*)d_in[4], (const float*)d_in[5],
        (const float*)d_in[6],  (const float*)d_in[7], (const float*)d_in[8],
        (const float*)d_in[9],  (const float*)d_in[10], (float*)d_out);
}

// round 2
// speedup vs baseline: 1.1291x; 1.1291x over previous
#include <cuda_runtime.h>

#define T_STEPS 32
#define BB      32
#define NIN     512
#define NH      1024
#define NOUT    256
#define NBLK    148
#define NTHR    512
#define KC      64

// ---------------- device scratch ----------------
__device__ float g_hist[T_STEPS][BB][NH];   // pre-norm h history (4 MB)
__device__ float g_h[BB][NH];               // carry (normalized hs)
__device__ float g_sP[2][BB][NH];
__device__ float g_hWP[2][BB][NH];
__device__ float g_zP[4][BB][NH];
__device__ float g_zcP[4][BB][NH];
__device__ float g_zc[BB][NH];
__device__ float g_hsP[4][BB][NH];
__device__ float g_dots[T_STEPS][BB];
__device__ unsigned g_cnt;                  // monotonic barrier counter

// ---------------- f32x2 helpers ----------------
__device__ __forceinline__ unsigned long long pk2(float lo, float hi) {
    unsigned long long r;
    asm("mov.b64 %0, {%1, %2};" : "=l"(r) : "f"(lo), "f"(hi));
    return r;
}
__device__ __forceinline__ void upk2(unsigned long long v, float& lo, float& hi) {
    asm("mov.b64 {%0, %1}, %2;" : "=f"(lo), "=f"(hi) : "l"(v));
}
__device__ __forceinline__ unsigned long long fma2(unsigned long long a,
                                                   unsigned long long b,
                                                   unsigned long long c) {
    unsigned long long d;
    asm("fma.rn.f32x2 %0, %1, %2, %3;" : "=l"(d) : "l"(a), "l"(b), "l"(c));
    return d;
}

// ---------------- grid barrier ----------------
__device__ __forceinline__ void gsync() {
    __syncthreads();
    if (threadIdx.x == 0) {
        __threadfence();
        unsigned arrival = atomicAdd(&g_cnt, 1u);
        unsigned target  = (arrival / NBLK + 1u) * NBLK;
        while (*(volatile unsigned*)&g_cnt < target) { }
        __threadfence();
    }
    __syncthreads();
}

// ---------------- 32 x klen x 32-col GEMM tile --------------------------
// out[b][j] = sum_{k in [k0,k0+klen)} A[b][k] * W[k][j], j in chunk*32..+31.
// A combined from up to 4 partial buffers w/ optional relu at staging.
// 512 threads: 16 warps x 2 rows, 1 fma2 chain per thread.
template<int NSUM, bool RELU, int KA, int N>
__device__ __forceinline__ void gemm32(float (*As)[34],
    const float* __restrict__ A0, const float* __restrict__ A1,
    const float* __restrict__ A2, const float* __restrict__ A3,
    const float* __restrict__ W, int k0, int klen,
    float* __restrict__ outp, int chunk)
{
    const int tid  = threadIdx.x;
    const int lane = tid & 31;
    const int wg   = tid >> 5;          // 16 warps -> 2 rows each
    const int j    = chunk * 32 + lane;
    const int r0   = wg * 2;
    unsigned long long acc = 0ULL;

    for (int kb = 0; kb < klen; kb += KC) {
        __syncthreads();
#pragma unroll
        for (int u = 0; u < (KC * BB) / NTHR; ++u) {   // 4
            int idx = u * NTHR + tid;
            int b   = idx >> 6;
            int kk  = idx & (KC - 1);
            int gk  = k0 + kb + kk;
            float v = A0[b * KA + gk];
            if (NSUM > 1) v += A1[b * KA + gk];
            if (NSUM > 2) v += A2[b * KA + gk];
            if (NSUM > 3) v += A3[b * KA + gk];
            if (RELU) v = fmaxf(v, 0.0f);
            As[kk][b] = v;
        }
        __syncthreads();
        const float* Wp = W + (k0 + kb) * N + j;
#pragma unroll 16
        for (int kk = 0; kk < KC; ++kk) {
            float w = Wp[kk * N];                       // coalesced, imm offset
            unsigned long long w2 = pk2(w, w);
            unsigned long long a  = *(const unsigned long long*)&As[kk][r0];
            acc = fma2(a, w2, acc);
        }
    }
    float s0, s1;
    upk2(acc, s0, s1);
    outp[(r0 + 0) * N + j] = s0;
    outp[(r0 + 1) * N + j] = s1;
}

// ---------------- persistent kernel ------------------------------------
__global__ void __launch_bounds__(NTHR, 1) memnet_kernel(
    const float* __restrict__ x_in,  const float* __restrict__ W_i,
    const float* __restrict__ W_z,   const float* __restrict__ W_c,
    const float* __restrict__ W_h,   const float* __restrict__ W_ho,
    const float* __restrict__ W_o,   const float* __restrict__ lam_p,
    const float* __restrict__ eta_p, const float* __restrict__ g_p,
    const float* __restrict__ b_p,   float* __restrict__ y_out)
{
    __shared__ float As[KC][34];
    __shared__ float red_s[16][32];
    __shared__ float red_q[16][32];

    const int tid  = threadIdx.x;
    const int bid  = blockIdx.x;
    const int lane = tid & 31;
    const int wg   = tid >> 5;
    const int gtid = bid * NTHR + tid;
    const int gstr = NBLK * NTHR;

    // ---- prologue: zero carry + s partials for t=0 (relu(x0)@W_i)
    for (int i = gtid; i < BB * NH; i += gstr) (&g_h[0][0])[i] = 0.0f;
    if (bid < 64) {
        int chunk = bid >> 1, kh = bid & 1;
        gemm32<1, true, NIN, NH>(As, x_in, 0, 0, 0, W_i,
                                 kh * 256, 256, &g_sP[kh][0][0], chunk);
    }
    gsync();

    const float lamv = lam_p[0];
    const float etav = eta_p[0];

    for (int t = 0; t < T_STEPS; ++t) {
        // ---- P1: hW partials (h@W_h, 64 tasks) + z partials (relu(s)@W_z, 128)
        for (int task = bid; task < 192; task += NBLK) {
            if (task < 64) {
                int chunk = task >> 1, kh = task & 1;
                gemm32<1, false, NH, NH>(As, &g_h[0][0], 0, 0, 0, W_h,
                                         kh * 512, 512, &g_hWP[kh][0][0], chunk);
            } else {
                int tt = task - 64;
                int chunk = tt >> 2, ks = tt & 3;
                gemm32<2, true, NH, NH>(As, &g_sP[0][0][0], &g_sP[1][0][0], 0, 0,
                                        W_z, ks * 256, 256, &g_zP[ks][0][0], chunk);
            }
        }
        gsync();

        // ---- P2: zc partials = relu(z) @ W_c
        for (int task = bid; task < 128; task += NBLK) {
            int chunk = task >> 2, ks = task & 3;
            gemm32<4, true, NH, NH>(As, &g_zP[0][0][0], &g_zP[1][0][0],
                                    &g_zP[2][0][0], &g_zP[3][0][0],
                                    W_c, ks * 256, 256, &g_zcP[ks][0][0], chunk);
        }
        gsync();

        // ---- P3: elementwise h_new = relu(zc + hW), keep zc
        {
            const float* zc0 = &g_zcP[0][0][0]; const float* zc1 = &g_zcP[1][0][0];
            const float* zc2 = &g_zcP[2][0][0]; const float* zc3 = &g_zcP[3][0][0];
            const float* hw0 = &g_hWP[0][0][0]; const float* hw1 = &g_hWP[1][0][0];
            float* zcs = &g_zc[0][0];
            float* hn  = &g_hist[t][0][0];
            for (int i = gtid; i < BB * NH; i += gstr) {
                float zc = (zc0[i] + zc1[i]) + (zc2[i] + zc3[i]);
                float hw = hw0[i] + hw1[i];
                zcs[i] = zc;
                hn[i]  = fmaxf(zc + hw, 0.0f);
            }
        }
        gsync();

        // ---- P4: hs partials = h_new @ W_h (128 tasks) + history dots
        for (int task = bid; task < 128; task += NBLK) {
            int chunk = task >> 2, ks = task & 3;
            gemm32<1, false, NH, NH>(As, &g_hist[t][0][0], 0, 0, 0, W_h,
                                     ks * 256, 256, &g_hsP[ks][0][0], chunk);
        }
        if (bid >= 128) {   // 20 blocks x 16 warps: dots[s][b] = h_t . h_s
            int widg = (bid - 128) * 16 + wg;
            int nd = (t + 1) * BB;
            for (int d = widg; d < nd; d += 20 * 16) {
                int s = d >> 5, b = d & 31;
                const float* ha = &g_hist[t][b][0];
                const float* hb = &g_hist[s][b][0];
                float sum = 0.0f;
#pragma unroll
                for (int jj = lane * 4; jj < NH; jj += 128) {
                    float4 a = *(const float4*)(ha + jj);
                    float4 c = *(const float4*)(hb + jj);
                    sum += a.x * c.x + a.y * c.y + a.z * c.z + a.w * c.w;
                }
#pragma unroll
                for (int off = 16; off; off >>= 1)
                    sum += __shfl_xor_sync(0xffffffffu, sum, off);
                if (lane == 0) g_dots[s][b] = sum;
            }
        }
        gsync();

        // ---- P5: norm (32 tasks) + precompute s_{t+1} (64 tasks on idle CTAs)
        if (bid < 32) {
            int j = bid * 32 + lane;
            float gv = g_p[j], bv = b_p[j];
            float v[2];
#pragma unroll
            for (int r = 0; r < 2; ++r) {
                int b = wg * 2 + r;
                float base = (g_hsP[0][b][j] + g_hsP[1][b][j]) +
                             (g_hsP[2][b][j] + g_hsP[3][b][j]) + g_zc[b][j];
                float accr = 0.0f, p = 1.0f;
#pragma unroll 4
                for (int s = t; s >= 0; --s) {
                    accr += p * g_dots[s][b] * g_hist[s][b][j];
                    p *= lamv;
                }
                v[r] = base + etav * accr;
            }
            float ps = v[0] + v[1];
            float pq = v[0] * v[0] + v[1] * v[1];
            red_s[wg][lane] = ps;
            red_q[wg][lane] = pq;
            __syncthreads();
            float mu = 0.0f, sq = 0.0f;
#pragma unroll
            for (int w = 0; w < 16; ++w) { mu += red_s[w][lane]; sq += red_q[w][lane]; }
            mu *= (1.0f / BB);
            sq *= (1.0f / BB);
            float sig = sqrtf(fmaxf(sq - mu * mu, 0.0f));
#pragma unroll
            for (int r = 0; r < 2; ++r) {
                float hv = fmaxf(gv * (v[r] - mu) / sig + bv, 0.0f);
                g_h[wg * 2 + r][j] = hv;
            }
        } else if (bid >= 32 && bid < 96 && t < T_STEPS - 1) {
            const float* xt1 = x_in + (size_t)(t + 1) * BB * NIN;
            int tt = bid - 32;
            int chunk = tt >> 1, kh = tt & 1;
            gemm32<1, true, NIN, NH>(As, xt1, 0, 0, 0, W_i,
                                     kh * 256, 256, &g_sP[kh][0][0], chunk);
        }
        gsync();
    }

    // ---- F1: o partials = h @ W_ho (relu deferred to F2 staging)
    for (int task = bid; task < 128; task += NBLK) {
        int chunk = task >> 2, ks = task & 3;
        gemm32<1, false, NH, NH>(As, &g_h[0][0], 0, 0, 0, W_ho,
                                 ks * 256, 256, &g_zP[ks][0][0], chunk);
    }
    gsync();

    // ---- F2: y partials = relu(o) @ W_o
    for (int task = bid; task < 32; task += NBLK) {
        int chunk = task >> 2, ks = task & 3;
        gemm32<4, true, NH, NOUT>(As, &g_zP[0][0][0], &g_zP[1][0][0],
                                  &g_zP[2][0][0], &g_zP[3][0][0],
                                  W_o, ks * 256, 256,
                                  (&g_zcP[0][0][0]) + (size_t)ks * BB * NOUT, chunk);
    }
    gsync();

    // ---- F3: y = relu(sum partials)
    {
        const float* yp = &g_zcP[0][0][0];
        for (int i = gtid; i < BB * NOUT; i += gstr) {
            float v = (yp[i] + yp[BB * NOUT + i]) +
                      (yp[2 * BB * NOUT + i] + yp[3 * BB * NOUT + i]);
            y_out[i] = fmaxf(v, 0.0f);
        }
    }
}

// ---------------- launch ----------------
extern "C" void kernel_launch(void* const* d_in, const int* in_sizes, int n_in,
                              void* d_out, int out_size) {
    (void)in_sizes; (void)n_in; (void)out_size;
    memnet_kernel<<<NBLK, NTHR>>>(
        (const float*)d_in[0],  (const float*)d_in[1], (const float*)d_in[2],
        (const float*)d_in[3],  (const float*)d_in[4], (const float*)d_in[5],
        (const float*)d_in[6],  (const float*)d_in[7], (const float*)d_in[8],
        (const float*)d_in[9],  (const float*)d_in[10], (float*)d_out);
}